// round 12
// baseline (speedup 1.0000x reference)
#include <cuda_runtime.h>
#include <cuda_fp16.h>
#include <math.h>

#define VOL (128*128*128)          // 2^21
#define NB 8                        // batch*channels

// Packed spectra FFT(o + i*t): [vol][p][z][y] where plane p holds true kx=rev7(p)
__device__ __half2 g_ft[(size_t)NB * VOL];
// Accumulators: c3*520 + shell*8 + bc
__device__ float g_acc[3 * 65 * NB];
__device__ unsigned g_done;

__device__ __forceinline__ int rev5(int i) { return (int)(__brev((unsigned)i) >> 27); }
__device__ __forceinline__ int rev7(int i) { return (int)(__brev((unsigned)i) >> 25); }

// ===========================================================================
// SoA fp16 twiddle tables: per twiddle w=(wr,wi): rr=(wr,wr), iin=(-wi,-wi),
// iip=(wi,wi). 16B entries -> one LDS.128. 1/sqrt(128) folded into twS[3].
struct __align__(16) h2quad { __half2 rr, iin, iip, pad; };
#define TABS_Q (64 + 32 + 128)

__device__ __forceinline__ void set_q(h2quad& q, float c, float s, float g) {
    // w = (c, s) scaled by g   (s here is the signed imaginary part)
    q.rr  = __floats2half2_rn(c * g, c * g);
    q.iin = __floats2half2_rn(-s * g, -s * g);
    q.iip = __floats2half2_rn(s * g, s * g);
    q.pad = __floats2half2_rn(0.f, 0.f);
}

__device__ __forceinline__ void init_tabs_q(h2quad* twA, h2quad* twB, h2quad* twS, int tid) {
    const float K = -0.04908738521234052f;   // -2*pi/128
    const float SC = 0.08838834764831845f;   // 1/sqrt(128)
    if (tid < 64) {
        float sv, cv; sincosf(K * (float)tid, &sv, &cv);
        set_q(twA[tid], cv, sv, 1.0f);
    }
    if (tid < 32) {
        float sv, cv; sincosf(K * (float)(2 * tid), &sv, &cv);
        set_q(twB[tid], cv, sv, 1.0f);
#pragma unroll
        for (int j = 0; j < 4; j++) {
            int m = 16 >> j;
            float c2 = 1.0f, s2 = 0.0f;
            if (tid & m) {
                int idx = (tid & (m - 1)) * (64 / m);
                sincosf(K * (float)idx, &s2, &c2);
            }
            set_q(twS[j * 32 + tid], c2, s2, (j == 3) ? SC : 1.0f);
        }
    }
}

__device__ __forceinline__ void cmul_soa(const h2quad& w, __half2& re, __half2& im) {
    __half2 r = __hfma2(w.iin, im, __hmul2(w.rr, re));
    __half2 i = __hfma2(w.iip, re, __hmul2(w.rr, im));
    re = r; im = i;
}
__device__ __forceinline__ __half2 shflx_h2(__half2 v, int m) {
    unsigned u = *reinterpret_cast<unsigned*>(&v);
    u = __shfl_xor_sync(0xffffffffu, u, m);
    return *reinterpret_cast<__half2*>(&u);
}
__device__ __forceinline__ __half2 sgn_h2(int hi) {
    unsigned u = hi ? 0xBC00BC00u : 0x3C003C00u;   // (-1,-1) : (1,1)
    return *reinterpret_cast<__half2*>(&u);
}
__device__ __forceinline__ unsigned h2u(__half2 v) { return *reinterpret_cast<unsigned*>(&v); }
__device__ __forceinline__ __half2 u2h(unsigned u) { return *reinterpret_cast<__half2*>(&u); }

// TWO interleaved 128-pt DIF FFTs, SoA: re[r] = (re_fft0, re_fft1), im likewise.
// Slot (lane,r) holds x[lane+32r] in, sc*X[rev7(lane+32r)] out.
__device__ __forceinline__ void dif_fft128_soa(__half2 re[4], __half2 im[4], int lane,
        const h2quad* twA, const h2quad* twB, const h2quad* twS) {
    __half2 ar, ai, br, bi;
    {
        h2quad w0 = twA[lane], w1 = twA[lane + 32];
        ar = re[0]; ai = im[0]; br = re[2]; bi = im[2];
        re[0] = __hadd2(ar, br); im[0] = __hadd2(ai, bi);
        re[2] = __hsub2(ar, br); im[2] = __hsub2(ai, bi);
        cmul_soa(w0, re[2], im[2]);
        ar = re[1]; ai = im[1]; br = re[3]; bi = im[3];
        re[1] = __hadd2(ar, br); im[1] = __hadd2(ai, bi);
        re[3] = __hsub2(ar, br); im[3] = __hsub2(ai, bi);
        cmul_soa(w1, re[3], im[3]);
    }
    {
        h2quad w0 = twB[lane];
        ar = re[0]; ai = im[0]; br = re[1]; bi = im[1];
        re[0] = __hadd2(ar, br); im[0] = __hadd2(ai, bi);
        re[1] = __hsub2(ar, br); im[1] = __hsub2(ai, bi);
        cmul_soa(w0, re[1], im[1]);
        ar = re[2]; ai = im[2]; br = re[3]; bi = im[3];
        re[2] = __hadd2(ar, br); im[2] = __hadd2(ai, bi);
        re[3] = __hsub2(ar, br); im[3] = __hsub2(ai, bi);
        cmul_soa(w0, re[3], im[3]);
    }
#pragma unroll
    for (int j = 0; j < 4; j++) {
        int m = 16 >> j;
        __half2 sg = sgn_h2(lane & m);
        h2quad wj = twS[j * 32 + lane];
#pragma unroll
        for (int r = 0; r < 4; r++) {
            __half2 ore = shflx_h2(re[r], m);
            __half2 oim = shflx_h2(im[r], m);
            re[r] = __hfma2(sg, re[r], ore);
            im[r] = __hfma2(sg, im[r], oim);
            cmul_soa(wj, re[r], im[r]);
        }
    }
    {
        __half2 sg = sgn_h2(lane & 1);
#pragma unroll
        for (int r = 0; r < 4; r++) {
            __half2 ore = shflx_h2(re[r], 1);
            __half2 oim = shflx_h2(im[r], 1);
            re[r] = __hfma2(sg, re[r], ore);
            im[r] = __hfma2(sg, im[r], oim);
        }
    }
}

// ---------------------------------------------------------------------------
// Pass 1: pack P = o + i*t, x-FFT fp16 SoA (2 rows per warp), fp16 (re,im)
// transposed to [vol][p][z][y].
__global__ void __launch_bounds__(1024) k_fft_x(const float* __restrict__ a_in,
                                                const float* __restrict__ b_in) {
    __shared__ h2quad tabs[TABS_Q];
    __shared__ __half2 tile[64][129];
    h2quad* twA = tabs; h2quad* twB = tabs + 64; h2quad* twS = tabs + 96;
    int tid = threadIdx.x, lane = tid & 31, w = tid >> 5;
    init_tabs_q(twA, twB, twS, tid);

    unsigned b = blockIdx.x;              // 8 vols * 128 z * 2 ytiles = 2048
    unsigned ytile = b & 1u;
    unsigned z     = (b >> 1) & 127u;
    unsigned vol   = b >> 8;

    size_t off = (size_t)vol * VOL + (size_t)z * 16384 + (size_t)(ytile * 64 + w) * 128;
    const float* so0 = a_in + off;               // row w      : o
    const float* st0 = b_in + off;               // row w      : t
    const float* so1 = so0 + 32 * 128;           // row w+32   : o
    const float* st1 = st0 + 32 * 128;
    __syncthreads();

    // SoA directly: re=(o_row0, o_row1), im=(t_row0, t_row1)
    __half2 re[4], im[4];
#pragma unroll
    for (int r = 0; r < 4; r++) {
        int e = lane + 32 * r;
        re[r] = __floats2half2_rn(so0[e], so1[e]);
        im[r] = __floats2half2_rn(st0[e], st1[e]);
    }
    dif_fft128_soa(re, im, lane, twA, twB, twS);

#pragma unroll
    for (int r = 0; r < 4; r++) {
        int e = lane + 32 * r;
        tile[w][e]      = u2h(__byte_perm(h2u(re[r]), h2u(im[r]), 0x5410));
        tile[w + 32][e] = u2h(__byte_perm(h2u(re[r]), h2u(im[r]), 0x7632));
    }
    __syncthreads();

    size_t base = (size_t)vol * VOL + (size_t)z * 128 + ytile * 64 + lane;
#pragma unroll
    for (int xi = 0; xi < 4; xi++) {
        int p = w * 4 + xi;               // bit-reversed kx label
        g_ft[base + (size_t)p * 16384]      = tile[lane][p];
        g_ft[base + (size_t)p * 16384 + 32] = tile[lane + 32][p];
    }
}

// ---------------------------------------------------------------------------
// Pass 2: per (bc, true-kx pair): y-FFT reads directly from global into SoA
// registers, writes (re,im) to smem; z-FFT SoA in registers (column + conj-
// mirror column, same-lane Hermitian pairing via lo/hi halves); fp32 reduce.
#define SMEM2 (TABS_Q * 16 + 2 * 128 * 129 * 4 + 32 * 196 * 4)

__global__ void __launch_bounds__(1024, 1) k_fft_yz_reduce(float* __restrict__ out) {
    extern __shared__ unsigned char smem_raw[];
    h2quad*  tabs = (h2quad*)smem_raw;
    h2quad*  twA = tabs; h2quad* twB = tabs + 64; h2quad* twS = tabs + 96;
    __half2* pA   = (__half2*)(tabs + TABS_Q);            // [z][y] pitch 129
    __half2* pBs  = pA + 128 * 129;
    float*   bins = (float*)(pBs + 128 * 129);            // [warp][196]
    __shared__ bool s_last;
    __shared__ float red[NB];

    int tid = threadIdx.x, lane = tid & 31, w = tid >> 5;
    init_tabs_q(twA, twB, twS, tid);
    for (int i = tid; i < 32 * 196; i += 1024) bins[i] = 0.0f;

    unsigned bc  = blockIdx.x / 65;
    unsigned kx1 = blockIdx.x % 65;                       // true kx 0..64
    unsigned kx2 = (128u - kx1) & 127u;
    bool dual = (kx2 != kx1);
    int p1 = rev7((int)kx1), p2 = rev7((int)kx2);
    __half2* pB = dual ? pBs : pA;

    const __half2* gA = g_ft + ((size_t)bc * 128 + p1) * 16384;
    const __half2* gB = g_ft + ((size_t)bc * 128 + p2) * 16384;
    __syncthreads();                       // tables + bins ready

    // y-FFT: rows straight from global -> SoA -> FFT -> (re,im) to smem.
    if (dual) {
#pragma unroll
        for (int i = 0; i < 4; i++) {
            int z = w + 32 * i;
            __half2 re[4], im[4];
#pragma unroll
            for (int r = 0; r < 4; r++) {
                unsigned a = h2u(gA[z * 128 + lane + 32 * r]);
                unsigned b = h2u(gB[z * 128 + lane + 32 * r]);
                re[r] = u2h(__byte_perm(a, b, 0x5410));
                im[r] = u2h(__byte_perm(a, b, 0x7632));
            }
            dif_fft128_soa(re, im, lane, twA, twB, twS);
#pragma unroll
            for (int r = 0; r < 4; r++) {
                int e = lane + 32 * r;
                pA [z * 129 + e] = u2h(__byte_perm(h2u(re[r]), h2u(im[r]), 0x5410));
                pBs[z * 129 + e] = u2h(__byte_perm(h2u(re[r]), h2u(im[r]), 0x7632));
            }
        }
    } else {
#pragma unroll
        for (int i = 0; i < 2; i++) {
            int z0 = w + 64 * i, z1 = z0 + 32;
            __half2 re[4], im[4];
#pragma unroll
            for (int r = 0; r < 4; r++) {
                unsigned a = h2u(gA[z0 * 128 + lane + 32 * r]);
                unsigned b = h2u(gA[z1 * 128 + lane + 32 * r]);
                re[r] = u2h(__byte_perm(a, b, 0x5410));
                im[r] = u2h(__byte_perm(a, b, 0x7632));
            }
            dif_fft128_soa(re, im, lane, twA, twB, twS);
#pragma unroll
            for (int r = 0; r < 4; r++) {
                int e = lane + 32 * r;
                pA[z0 * 129 + e] = u2h(__byte_perm(h2u(re[r]), h2u(im[r]), 0x5410));
                pA[z1 * 129 + e] = u2h(__byte_perm(h2u(re[r]), h2u(im[r]), 0x7632));
            }
        }
    }
    __syncthreads();

    // z-FFT SoA: fft0 = column pyA of A, fft1 = conj(mirror column pyB of B).
    // Then F = lo halves, H = conj(F(-k)) = hi halves, same slot.
    // slot (lane,r) holds kz = 4*rev5(lane) + {0,2,1,3}[r]
    int fx = (int)kx1; if (fx >= 64) fx -= 128;
    float cfac = dual ? 0.5f : 0.25f;     // z-norm inside the FFT scale
    float* mybins = bins + w * 196;
    const __half2 cnj = u2h(0xBC003C00u);  // (1, -1): negate hi (imH)

    int qz = rev5(lane);
    int kzv[4] = { 4 * qz, 4 * qz + 2, 4 * qz + 1, 4 * qz + 3 };
    int fzv[4];
#pragma unroll
    for (int r = 0; r < 4; r++) fzv[r] = (kzv[r] >= 64) ? kzv[r] - 128 : kzv[r];

#pragma unroll
    for (int i = 0; i < 4; i++) {
        int pyA = w + 32 * i;                 // column position (bit-reversed ky)
        int kyA = rev7(pyA);
        int fy = (kyA >= 64) ? kyA - 128 : kyA;
        int fxy2 = fx * fx + fy * fy;
        if (fxy2 > 4224) continue;            // no shell <= 64 possible (warp-uniform)
        int pyB = rev7((128 - kyA) & 127);

        __half2 re[4], im[4];
#pragma unroll
        for (int r = 0; r < 4; r++) {
            unsigned a = h2u(pA[(lane + 32 * r) * 129 + pyA]);
            unsigned b = h2u(pB[(lane + 32 * r) * 129 + pyB]);
            re[r] = u2h(__byte_perm(a, b, 0x5410));
            im[r] = __hmul2(u2h(__byte_perm(a, b, 0x7632)), cnj);
        }
        dif_fft128_soa(re, im, lane, twA, twB, twS);

#pragma unroll
        for (int r = 0; r < 4; r++) {
            int r2 = fzv[r] * fzv[r] + fxy2;
            int sh = (int)sqrtf((float)r2);    // exact truncation
            if (sh <= 64) {
                float2 fre = __half22float2(re[r]);   // (reF, reH)
                float2 fim = __half22float2(im[r]);   // (imF, imH)
                float Ox = fre.x + fre.y, Oy = fim.x + fim.y;   // 2*O
                float Tx = fim.x - fim.y, Ty = fre.y - fre.x;   // 2*T
                atomicAdd(&mybins[sh * 3 + 0], Ox * Tx + Oy * Ty);
                atomicAdd(&mybins[sh * 3 + 1], Ox * Ox + Oy * Oy);
                atomicAdd(&mybins[sh * 3 + 2], Tx * Tx + Ty * Ty);
            }
        }
    }
    __syncthreads();

    // fold per-warp bins -> global accumulators (cfac applied once here)
    if (tid < 195) {
        float s = 0.0f;
#pragma unroll
        for (int ww = 0; ww < 32; ww++) s += bins[ww * 196 + tid];
        int sh = tid / 3, c3 = tid % 3;
        atomicAdd(&g_acc[c3 * 520 + sh * 8 + bc], s * cfac);
    }
    __syncthreads();

    // last block computes loss and resets state (graph-replay safe)
    if (tid == 0) {
        __threadfence();
        unsigned old = atomicAdd(&g_done, 1u);
        s_last = (old == gridDim.x - 1);
    }
    __syncthreads();
    if (!s_last) return;

    float* sacc = bins;
    for (int i = tid; i < 3 * 65 * NB; i += 1024)
        sacc[i] = atomicExch(&g_acc[i], 0.0f);
    __syncthreads();

    if (tid < NB) {
        float acc = 0.0f;
        for (int s = 1; s <= 64; s++) {
            float n  = sacc[0 * 520 + s * 8 + tid];
            float po = sacc[1 * 520 + s * 8 + tid];
            float pt = sacc[2 * 520 + s * 8 + tid];
            float f = n / sqrtf(po * pt + 1e-6f);
            acc += fminf(1.0f, fmaxf(-1.0f, f));
        }
        red[tid] = 1.0f - acc * (1.0f / 64.0f);
    }
    __syncthreads();
    if (tid == 0) {
        float m = 0.0f;
#pragma unroll
        for (int i = 0; i < NB; i++) m += red[i];
        out[0] = m * (1.0f / (float)NB);
        atomicExch(&g_done, 0u);
    }
}

// ---------------------------------------------------------------------------
extern "C" void kernel_launch(void* const* d_in, const int* in_sizes, int n_in,
                              void* d_out, int out_size) {
    const float* model_output = (const float*)d_in[0];
    const float* target       = (const float*)d_in[1];

    cudaFuncSetAttribute(k_fft_yz_reduce,
                         cudaFuncAttributeMaxDynamicSharedMemorySize, SMEM2);

    k_fft_x<<<8 * 128 * 2, 1024>>>(model_output, target);
    k_fft_yz_reduce<<<8 * 65, 1024, SMEM2>>>((float*)d_out);
}

// round 13
// speedup vs baseline: 1.5973x; 1.5973x over previous
#include <cuda_runtime.h>
#include <cuda_fp16.h>
#include <math.h>

#define VOL (128*128*128)          // 2^21
#define NB 8                        // batch*channels
#define NUNITS (NB * 65)            // 520 work units in pass 2

// Packed spectra FFT(o + i*t): [vol][p][z][y] where plane p holds true kx=rev7(p)
__device__ __half2 g_ft[(size_t)NB * VOL];
// Accumulators: c3*520 + shell*8 + bc
__device__ float g_acc[3 * 65 * NB];
__device__ unsigned g_done;
__device__ unsigned g_unit;        // dynamic work counter (reset by finalizer)

__device__ __forceinline__ int rev5(int i) { return (int)(__brev((unsigned)i) >> 27); }
__device__ __forceinline__ int rev7(int i) { return (int)(__brev((unsigned)i) >> 25); }

// ===========================================================================
// fp16 twiddle tables. Twiddle stored as pair (wr,wr),(-wi,wi).
// The 1/sqrt(128) ortho scale is folded into the m=2 stage table (twS[3]).
struct __align__(8) h2pair { __half2 rr, ii; };
#define TABS_H (64 + 32 + 128)

__device__ __forceinline__ void init_tabs_h(h2pair* twA, h2pair* twB, h2pair* twS, int tid) {
    const float K = -0.04908738521234052f;   // -2*pi/128
    const float SC = 0.08838834764831845f;   // 1/sqrt(128)
    if (tid < 64) {
        float sv, cv; sincosf(K * (float)tid, &sv, &cv);
        twA[tid].rr = __floats2half2_rn(cv, cv);
        twA[tid].ii = __floats2half2_rn(-sv, sv);
    }
    if (tid < 32) {
        float sv, cv; sincosf(K * (float)(2 * tid), &sv, &cv);
        twB[tid].rr = __floats2half2_rn(cv, cv);
        twB[tid].ii = __floats2half2_rn(-sv, sv);
#pragma unroll
        for (int j = 0; j < 4; j++) {
            int m = 16 >> j;
            float c2 = 1.0f, s2 = 0.0f;
            if (tid & m) {
                int idx = (tid & (m - 1)) * (64 / m);
                sincosf(K * (float)idx, &s2, &c2);
            }
            float g = (j == 3) ? SC : 1.0f;    // fold ortho scale into m=2 stage
            twS[j * 32 + tid].rr = __floats2half2_rn(c2 * g, c2 * g);
            twS[j * 32 + tid].ii = __floats2half2_rn(-s2 * g, s2 * g);
        }
    }
}

__device__ __forceinline__ __half2 cmul_h(h2pair w, __half2 v) {
    return __hfma2(w.ii, __lowhigh2highlow(v), __hmul2(w.rr, v));
}
__device__ __forceinline__ __half2 shflx_h2(__half2 v, int m) {
    unsigned u = *reinterpret_cast<unsigned*>(&v);
    u = __shfl_xor_sync(0xffffffffu, u, m);
    return *reinterpret_cast<__half2*>(&u);
}
__device__ __forceinline__ __half2 sgn_h2(int hi) {
    unsigned u = hi ? 0xBC00BC00u : 0x3C003C00u;   // (-1,-1) : (1,1)
    return *reinterpret_cast<__half2*>(&u);
}
__device__ __forceinline__ __half2 conj_h2(__half2 v) {
    unsigned c = 0xBC003C00u;                      // (1, -1)
    return __hmul2(v, *reinterpret_cast<__half2*>(&c));
}

// TWO interleaved 128-pt DIF FFTs in fp16x2 (shared twiddles, 2x ILP).
// Slot (lane,r) holds x[lane+32r] in, sc*X[rev7(lane+32r)] out.
__device__ __forceinline__ void dif_fft128_h2(__half2 v[4], __half2 u[4], int lane,
        const h2pair* twA, const h2pair* twB, const h2pair* twS) {
    __half2 a, b;
    {
        h2pair w0 = twA[lane], w1 = twA[lane + 32];
        a = v[0]; b = v[2]; v[0] = __hadd2(a, b); v[2] = cmul_h(w0, __hsub2(a, b));
        a = u[0]; b = u[2]; u[0] = __hadd2(a, b); u[2] = cmul_h(w0, __hsub2(a, b));
        a = v[1]; b = v[3]; v[1] = __hadd2(a, b); v[3] = cmul_h(w1, __hsub2(a, b));
        a = u[1]; b = u[3]; u[1] = __hadd2(a, b); u[3] = cmul_h(w1, __hsub2(a, b));
    }
    {
        h2pair w0 = twB[lane];
        a = v[0]; b = v[1]; v[0] = __hadd2(a, b); v[1] = cmul_h(w0, __hsub2(a, b));
        a = v[2]; b = v[3]; v[2] = __hadd2(a, b); v[3] = cmul_h(w0, __hsub2(a, b));
        a = u[0]; b = u[1]; u[0] = __hadd2(a, b); u[1] = cmul_h(w0, __hsub2(a, b));
        a = u[2]; b = u[3]; u[2] = __hadd2(a, b); u[3] = cmul_h(w0, __hsub2(a, b));
    }
#pragma unroll
    for (int j = 0; j < 4; j++) {
        int m = 16 >> j;
        __half2 sg = sgn_h2(lane & m);
        h2pair wj = twS[j * 32 + lane];
#pragma unroll
        for (int r = 0; r < 4; r++) {
            __half2 o1 = shflx_h2(v[r], m);
            __half2 o2 = shflx_h2(u[r], m);
            v[r] = cmul_h(wj, __hfma2(sg, v[r], o1));
            u[r] = cmul_h(wj, __hfma2(sg, u[r], o2));
        }
    }
    {
        __half2 sg = sgn_h2(lane & 1);
#pragma unroll
        for (int r = 0; r < 4; r++) {
            __half2 o1 = shflx_h2(v[r], 1);
            __half2 o2 = shflx_h2(u[r], 1);
            v[r] = __hfma2(sg, v[r], o1);
            u[r] = __hfma2(sg, u[r], o2);
        }
    }
}

// ---------------------------------------------------------------------------
// Pass 1: pack P = o + i*t (fp16), x-FFT fp16 (2 rows per warp, interleaved),
// transposed to [vol][p][z][y].
__global__ void __launch_bounds__(1024) k_fft_x(const float* __restrict__ a_in,
                                                const float* __restrict__ b_in) {
    __shared__ h2pair tabs[TABS_H];
    __shared__ __half2 tile[64][129];
    h2pair* twA = tabs; h2pair* twB = tabs + 64; h2pair* twS = tabs + 96;
    int tid = threadIdx.x, lane = tid & 31, w = tid >> 5;
    init_tabs_h(twA, twB, twS, tid);

    unsigned b = blockIdx.x;              // 8 vols * 128 z * 2 ytiles = 2048
    unsigned ytile = b & 1u;
    unsigned z     = (b >> 1) & 127u;
    unsigned vol   = b >> 8;

    size_t off = (size_t)vol * VOL + (size_t)z * 16384 + (size_t)(ytile * 64 + w) * 128;
    const float* so = a_in + off;
    const float* st = b_in + off;
    __syncthreads();

    __half2 v[4], u[4];
#pragma unroll
    for (int r = 0; r < 4; r++) {
        v[r] = __floats2half2_rn(so[lane + 32 * r],        st[lane + 32 * r]);
        u[r] = __floats2half2_rn(so[lane + 32 * r + 4096], st[lane + 32 * r + 4096]);
    }
    dif_fft128_h2(v, u, lane, twA, twB, twS);

#pragma unroll
    for (int r = 0; r < 4; r++) {
        tile[w][lane + 32 * r]      = v[r];
        tile[w + 32][lane + 32 * r] = u[r];
    }
    __syncthreads();

    size_t base = (size_t)vol * VOL + (size_t)z * 128 + ytile * 64 + lane;
#pragma unroll
    for (int xi = 0; xi < 4; xi++) {
        int p = w * 4 + xi;               // bit-reversed kx label
        g_ft[base + (size_t)p * 16384]      = tile[lane][p];
        g_ft[base + (size_t)p * 16384 + 32] = tile[lane + 32][p];
    }
}

// ---------------------------------------------------------------------------
// Pass 2 (PERSISTENT): each block loops over dynamically-fetched (bc,kx) units.
// Per unit: y-FFT reads directly from global into registers, writes to smem;
// z-FFT in registers (column + conj-mirror column, same-lane Hermitian
// pairing); fp32 shell reduce. Last block computes the loss and resets state.
#define SMEM2 (TABS_H * 8 + 2 * 128 * 129 * 4 + 32 * 196 * 4)

__global__ void __launch_bounds__(1024, 1) k_fft_yz_reduce(float* __restrict__ out) {
    extern __shared__ unsigned char smem_raw[];
    h2pair*  tabs = (h2pair*)smem_raw;
    h2pair*  twA = tabs; h2pair* twB = tabs + 64; h2pair* twS = tabs + 96;
    __half2* pA   = (__half2*)(tabs + TABS_H);            // [z][y] pitch 129
    __half2* pBs  = pA + 128 * 129;
    float*   bins = (float*)(pBs + 128 * 129);            // [warp][196]
    __shared__ unsigned s_unit;
    __shared__ bool s_last;
    __shared__ float red[NB];

    int tid = threadIdx.x, lane = tid & 31, w = tid >> 5;
    init_tabs_h(twA, twB, twS, tid);

    int qz = rev5(lane);
    int fzv[4];
    {
        int kzv[4] = { 4 * qz, 4 * qz + 2, 4 * qz + 1, 4 * qz + 3 };
#pragma unroll
        for (int r = 0; r < 4; r++) fzv[r] = (kzv[r] >= 64) ? kzv[r] - 128 : kzv[r];
    }
    float* mybins = bins + w * 196;

    for (;;) {
        // fetch next unit + zero bins (bins reads of previous unit are behind
        // the post-fold barrier)
        if (tid == 0) s_unit = atomicAdd(&g_unit, 1u);
        for (int i = tid; i < 32 * 196; i += 1024) bins[i] = 0.0f;
        __syncthreads();
        unsigned unit = s_unit;
        if (unit >= NUNITS) break;

        unsigned bc  = unit / 65;
        unsigned kx1 = unit % 65;                       // true kx 0..64
        unsigned kx2 = (128u - kx1) & 127u;
        bool dual = (kx2 != kx1);
        int p1 = rev7((int)kx1), p2 = rev7((int)kx2);
        __half2* pB = dual ? pBs : pA;

        const __half2* gA = g_ft + ((size_t)bc * 128 + p1) * 16384;
        const __half2* gB = g_ft + ((size_t)bc * 128 + p2) * 16384;

        // y-FFT: rows read straight from global, results to smem.
        if (dual) {
#pragma unroll
            for (int i = 0; i < 4; i++) {
                int z = w + 32 * i;
                __half2 v[4], u[4];
#pragma unroll
                for (int r = 0; r < 4; r++) {
                    v[r] = gA[z * 128 + lane + 32 * r];
                    u[r] = gB[z * 128 + lane + 32 * r];
                }
                dif_fft128_h2(v, u, lane, twA, twB, twS);
#pragma unroll
                for (int r = 0; r < 4; r++) {
                    pA [z * 129 + lane + 32 * r] = v[r];
                    pBs[z * 129 + lane + 32 * r] = u[r];
                }
            }
        } else {
#pragma unroll
            for (int i = 0; i < 2; i++) {
                int z0 = w + 64 * i, z1 = z0 + 32;
                __half2 v[4], u[4];
#pragma unroll
                for (int r = 0; r < 4; r++) {
                    v[r] = gA[z0 * 128 + lane + 32 * r];
                    u[r] = gA[z1 * 128 + lane + 32 * r];
                }
                dif_fft128_h2(v, u, lane, twA, twB, twS);
#pragma unroll
                for (int r = 0; r < 4; r++) {
                    pA[z0 * 129 + lane + 32 * r] = v[r];
                    pA[z1 * 129 + lane + 32 * r] = u[r];
                }
            }
        }
        __syncthreads();

        // z-FFT (fp16, registers). Mirror value F(-k) via FFT of the
        // CONJUGATED mirror column; conj folds into O/T sign flips.
        // slot (lane,r) holds kz = 4*rev5(lane) + {0,2,1,3}[r]
        int fx = (int)kx1; if (fx >= 64) fx -= 128;
        float cfac = dual ? 0.5f : 0.25f;     // z-norm inside the FFT scale

#pragma unroll
        for (int i = 0; i < 4; i++) {
            int pyA = w + 32 * i;                 // column position (bit-reversed ky)
            int kyA = rev7(pyA);
            int fy = (kyA >= 64) ? kyA - 128 : kyA;
            int fxy2 = fx * fx + fy * fy;
            if (fxy2 > 4224) continue;            // no shell <= 64 (warp-uniform)
            int pyB = rev7((128 - kyA) & 127);

            __half2 va[4], vh[4];
#pragma unroll
            for (int r = 0; r < 4; r++) {
                va[r] = pA[(lane + 32 * r) * 129 + pyA];
                vh[r] = conj_h2(pB[(lane + 32 * r) * 129 + pyB]);
            }
            dif_fft128_h2(va, vh, lane, twA, twB, twS);

#pragma unroll
            for (int r = 0; r < 4; r++) {
                int r2 = fzv[r] * fzv[r] + fxy2;
                int sh = (int)sqrtf((float)r2);    // exact truncation
                if (sh <= 64) {
                    float2 F = __half22float2(va[r]);
                    float2 H = __half22float2(vh[r]);   // H = conj(F(-k))
                    float Ox = F.x + H.x, Oy = F.y + H.y;   // 2*O
                    float Tx = F.y - H.y, Ty = H.x - F.x;   // 2*T
                    atomicAdd(&mybins[sh * 3 + 0], Ox * Tx + Oy * Ty);
                    atomicAdd(&mybins[sh * 3 + 1], Ox * Ox + Oy * Oy);
                    atomicAdd(&mybins[sh * 3 + 2], Tx * Tx + Ty * Ty);
                }
            }
        }
        __syncthreads();

        // fold per-warp bins -> global accumulators (cfac applied once here)
        if (tid < 195) {
            float s = 0.0f;
#pragma unroll
            for (int ww = 0; ww < 32; ww++) s += bins[ww * 196 + tid];
            int sh = tid / 3, c3 = tid % 3;
            atomicAdd(&g_acc[c3 * 520 + sh * 8 + bc], s * cfac);
        }
        __syncthreads();    // fold reads complete before next unit's zeroing
    }

    // completion: last block computes loss and resets state (graph-replay safe)
    if (tid == 0) {
        __threadfence();
        unsigned old = atomicAdd(&g_done, 1u);
        s_last = (old == gridDim.x - 1);
    }
    __syncthreads();
    if (!s_last) return;

    float* sacc = bins;
    for (int i = tid; i < 3 * 65 * NB; i += 1024)
        sacc[i] = atomicExch(&g_acc[i], 0.0f);
    __syncthreads();

    if (tid < NB) {
        float acc = 0.0f;
        for (int s = 1; s <= 64; s++) {
            float n  = sacc[0 * 520 + s * 8 + tid];
            float po = sacc[1 * 520 + s * 8 + tid];
            float pt = sacc[2 * 520 + s * 8 + tid];
            float f = n / sqrtf(po * pt + 1e-6f);
            acc += fminf(1.0f, fmaxf(-1.0f, f));
        }
        red[tid] = 1.0f - acc * (1.0f / 64.0f);
    }
    __syncthreads();
    if (tid == 0) {
        float m = 0.0f;
#pragma unroll
        for (int i = 0; i < NB; i++) m += red[i];
        out[0] = m * (1.0f / (float)NB);
        atomicExch(&g_unit, 0u);
        atomicExch(&g_done, 0u);
    }
}

// ---------------------------------------------------------------------------
extern "C" void kernel_launch(void* const* d_in, const int* in_sizes, int n_in,
                              void* d_out, int out_size) {
    const float* model_output = (const float*)d_in[0];
    const float* target       = (const float*)d_in[1];

    static int nsm = 0;
    if (nsm == 0) {
        int dev = 0;
        cudaGetDevice(&dev);
        if (cudaDeviceGetAttribute(&nsm, cudaDevAttrMultiProcessorCount, dev)
                != cudaSuccess || nsm <= 0)
            nsm = 148;
    }

    cudaFuncSetAttribute(k_fft_yz_reduce,
                         cudaFuncAttributeMaxDynamicSharedMemorySize, SMEM2);

    k_fft_x<<<8 * 128 * 2, 1024>>>(model_output, target);
    k_fft_yz_reduce<<<nsm, 1024, SMEM2>>>((float*)d_out);
}